// round 7
// baseline (speedup 1.0000x reference)
#include <cuda_runtime.h>
#include <cstdint>

// DRGN network: enc -> MHA x2 -> GRU -> linear, one CTA per batch sample.
// fp32, packed f32x2 FFMA (k-paired), cp.async weight staging (sm_103a).

#define NH    4
#define DH    32
#define HID   128
#define NANT  64
#define INDIM 64
#define ACTD  20
#define BS    4096
#define NEGV  9000000000000000.0f
#define ATT_SCALE 0.17677669529663687f   // 1/sqrt(32)
#define TPB   256

#define WPITCH 130                 // scratch W pitch (words): lane stride 2 mod 32 -> conflict-free LDS.64

// ---- shared memory layout (float offsets) ----
#define OFF_B0  0
#define OFF_B1  8192
#define OFF_B2  16384
#define OFF_B3  24576
#define OFF_M   32768              // 64*64 mask
#define OFF_SCR 36864              // scratch: max(W native 128*130=16640, attn 64*65+32*65=6240)
#define SMEM_FLOATS (36864 + 16640)
#define SMEM_BYTES  (SMEM_FLOATS * 4)

// scratch sub-layout during attention
#define OFF_SS  0                  // 64 x 65
#define OFF_KT  4160               // 32 x 65

typedef unsigned long long ull;

struct Params {
    const float* x;
    const int*   mask;
    const float* hidden;
    const float* enc_w; const float* enc_b;
    const float* q1_w;  const float* q1_b;
    const float* k1_w;  const float* k1_b;
    const float* v1_w;  const float* v1_b;
    const float* o1_w;  const float* o1_b;
    const float* q2_w;  const float* q2_b;
    const float* k2_w;  const float* k2_b;
    const float* v2_w;  const float* v2_b;
    const float* o2_w;  const float* o2_b;
    const float* w_ih;  const float* w_hh;
    const float* b_ih;  const float* b_hh;
    const float* lin_w; const float* lin_b;
};

// ---- packed f32x2 helpers ----
__device__ __forceinline__ ull pack2(float x, float y) {
    ull r;
    asm("mov.b64 %0, {%1, %2};" : "=l"(r) : "r"(__float_as_uint(x)), "r"(__float_as_uint(y)));
    return r;
}
__device__ __forceinline__ void ffma2(ull& d, ull a, ull b) {
    asm("fma.rn.f32x2 %0, %1, %2, %0;" : "+l"(d) : "l"(a), "l"(b));
}
__device__ __forceinline__ float acc_sum(ull v) {        // lo (even-k) + hi (odd-k)
    unsigned lo, hi;
    asm("mov.b64 {%0, %1}, %2;" : "=r"(lo), "=r"(hi) : "l"(v));
    return __uint_as_float(lo) + __uint_as_float(hi);
}
__device__ __forceinline__ void zero_acc(ull* a) {
    #pragma unroll
    for (int i = 0; i < 32; i++) a[i] = 0ull;
}
__device__ __forceinline__ float sigmoid_f(float x) {
    return __fdividef(1.f, 1.f + __expf(-x));
}
__device__ __forceinline__ float tanh_f(float x) {
    float e = __expf(2.f * x);
    return 1.f - __fdividef(2.f, e + 1.f);
}

// ---- cp.async (LDGSTS.64) helpers ----
__device__ __forceinline__ void cpa8(uint32_t dst_smem, const float* src) {
    asm volatile("cp.async.ca.shared.global [%0], [%1], 8;\n" :: "r"(dst_smem), "l"(src));
}
__device__ __forceinline__ void cpa_commit() {
    asm volatile("cp.async.commit_group;\n");
}
template<int N>
__device__ __forceinline__ void cpa_wait() {
    asm volatile("cp.async.wait_group %0;\n" :: "n"(N));
}

// ---- GEMM pass: acc += A(64xK, pitch 128) @ W(gmem, [128][K] row-major)^T ----
// Thread tile: 8 rows x 4 cols.  tr = tid>>5 -> rows 8tr.. ; tc = tid&31 -> cols tc+32*cc.
// acc[i*4+cc] packs even/odd-k partial sums (f32x2 along k).
// W staged in NATIVE layout (rows c, pitch WPITCH) via cp.async, two k-chunks pipelined.

template<int K>
__device__ __forceinline__ void stage_chunk(uint32_t scr_u32, const float* __restrict__ gW,
                                            int k0, int tid)
{
    // 128 rows x 64 k = 4096 float-pairs; 16 LDGSTS.64 per thread
    #pragma unroll
    for (int j = 0; j < 16; j++) {
        int p  = tid + j * TPB;          // 0..4095
        int c  = p >> 5;
        int kp = (p & 31) * 2;
        cpa8(scr_u32 + (uint32_t)(c * WPITCH + k0 + kp) * 4, gW + c * K + k0 + kp);
    }
    cpa_commit();
}

__device__ __forceinline__ void fma_chunk(ull* acc, const float* sA, const float* scr,
                                          int k0, int tr, int tc)
{
    const float* a_base = sA + tr * 8 * HID;
    #pragma unroll 2
    for (int k = k0; k < k0 + 64; k += 4) {
        ull w01[4], w23[4];
        #pragma unroll
        for (int cc = 0; cc < 4; cc++) {
            const ull* wp = reinterpret_cast<const ull*>(scr + (tc + 32 * cc) * WPITCH + k);
            w01[cc] = wp[0];             // W[c][k], W[c][k+1]
            w23[cc] = wp[1];             // W[c][k+2], W[c][k+3]
        }
        #pragma unroll
        for (int i = 0; i < 8; i++) {
            float4 av = *reinterpret_cast<const float4*>(a_base + i * HID + k);
            ull a01 = pack2(av.x, av.y);
            ull a23 = pack2(av.z, av.w);
            #pragma unroll
            for (int cc = 0; cc < 4; cc++) {
                ffma2(acc[i * 4 + cc], a01, w01[cc]);
                ffma2(acc[i * 4 + cc], a23, w23[cc]);
            }
        }
    }
}

// K=128: two pipelined chunks. K=64 (encoder): single chunk.
template<int K>
__device__ __forceinline__ void gemm_pass(ull* acc, const float* sA,
                                          const float* __restrict__ gW,
                                          float* scr, uint32_t scr_u32, int tid)
{
    const int tr = tid >> 5, tc = tid & 31;
    __syncthreads();                     // prior scr users / A-buffer writers done
    if (K == 128) {
        stage_chunk<128>(scr_u32, gW, 0, tid);
        stage_chunk<128>(scr_u32, gW, 64, tid);
        cpa_wait<1>();                   // chunk0 landed
        __syncthreads();
        fma_chunk(acc, sA, scr, 0, tr, tc);
        cpa_wait<0>();                   // chunk1 landed
        __syncthreads();
        fma_chunk(acc, sA, scr, 64, tr, tc);
    } else {
        stage_chunk<64>(scr_u32, gW, 0, tid);
        cpa_wait<0>();
        __syncthreads();
        fma_chunk(acc, sA, scr, 0, tr, tc);
    }
}

// ---- epilogues (col c = tc + 32*cc) ----
__device__ __forceinline__ void epi_relu(const ull* acc, float* sC,
                                         const float* __restrict__ bias, int tid)
{
    const int tr = tid >> 5, tc = tid & 31;
    #pragma unroll
    for (int cc = 0; cc < 4; cc++) {
        int c = tc + 32 * cc;
        float b = bias[c];
        #pragma unroll
        for (int i = 0; i < 8; i++)
            sC[(tr * 8 + i) * HID + c] = fmaxf(acc_sum(acc[i * 4 + cc]) + b, 0.f);
    }
}

__device__ __forceinline__ void epi_sigmoid(const ull* acc, float* sC,
                                            const float* __restrict__ b1,
                                            const float* __restrict__ b2, int tid)
{
    const int tr = tid >> 5, tc = tid & 31;
    #pragma unroll
    for (int cc = 0; cc < 4; cc++) {
        int c = tc + 32 * cc;
        float b = b1[c] + b2[c];
        #pragma unroll
        for (int i = 0; i < 8; i++)
            sC[(tr * 8 + i) * HID + c] = sigmoid_f(acc_sum(acc[i * 4 + cc]) + b);
    }
}

// sRH[e] (currently r) <- r * (h_n + b_hh_n)   (same-thread in-place)
__device__ __forceinline__ void epi_rhn(const ull* acc, float* sRH,
                                        const float* __restrict__ bh, int tid)
{
    const int tr = tid >> 5, tc = tid & 31;
    #pragma unroll
    for (int cc = 0; cc < 4; cc++) {
        int c = tc + 32 * cc;
        float b = bh[c];
        #pragma unroll
        for (int i = 0; i < 8; i++) {
            int e = (tr * 8 + i) * HID + c;
            sRH[e] = sRH[e] * (acc_sum(acc[i * 4 + cc]) + b);
        }
    }
}

// n = tanh(i_n + b_ih_n + rhn); h3 = (1-z)*n + z*h  -> sRH (in place)
__device__ __forceinline__ void epi_gru_final(const ull* acc, const float* sH,
                                              float* sRH, const float* sZ,
                                              const float* __restrict__ bi, int tid)
{
    const int tr = tid >> 5, tc = tid & 31;
    #pragma unroll
    for (int cc = 0; cc < 4; cc++) {
        int c = tc + 32 * cc;
        float b = bi[c];
        #pragma unroll
        for (int i = 0; i < 8; i++) {
            int e = (tr * 8 + i) * HID + c;
            float n = tanh_f(acc_sum(acc[i * 4 + cc]) + b + sRH[e]);
            float z = sZ[e];
            sRH[e] = (1.f - z) * n + z * sH[e];
        }
    }
}

// ---- masked multi-head attention: O = softmax(mask(Q K^T / sqrt(dh))) V ----
__device__ void attention(const float* Qb, const float* Kb, const float* Vb,
                          float* Ob, const float* sM, float* scr, int tid)
{
    float* sS  = scr + OFF_SS;   // 64 x 65
    float* sKt = scr + OFF_KT;   // 32 x 65
    const int w = tid >> 5, l = tid & 31;
    for (int h = 0; h < NH; h++) {
        __syncthreads();                       // scratch reusable; K/V visible
        // stage K^T for this head: Kt[d][c] = K[c][h*32+d]
        for (int i = tid; i < NANT * DH; i += TPB) {
            int c = i >> 5, d = i & 31;
            sKt[d * 65 + c] = Kb[c * HID + h * DH + d];
        }
        __syncthreads();
        // scores: warp w -> rows 8w..8w+7; lane l -> cols l, l+32
        float accS[8][2];
        #pragma unroll
        for (int i = 0; i < 8; i++) { accS[i][0] = 0.f; accS[i][1] = 0.f; }
        for (int d = 0; d < DH; d += 4) {
            float k0[4], k1[4];
            #pragma unroll
            for (int dd = 0; dd < 4; dd++) {
                k0[dd] = sKt[(d + dd) * 65 + l];
                k1[dd] = sKt[(d + dd) * 65 + l + 32];
            }
            #pragma unroll
            for (int i = 0; i < 8; i++) {
                float4 q = *reinterpret_cast<const float4*>(Qb + (w*8 + i) * HID + h * DH + d);
                accS[i][0] += q.x*k0[0] + q.y*k0[1] + q.z*k0[2] + q.w*k0[3];
                accS[i][1] += q.x*k1[0] + q.y*k1[1] + q.z*k1[2] + q.w*k1[3];
            }
        }
        #pragma unroll
        for (int i = 0; i < 8; i++) {
            int r = w * 8 + i;
            #pragma unroll
            for (int j = 0; j < 2; j++) {
                int c = l + j * 32;
                float m = sM[r * 64 + c];
                float s = accS[i][j] * ATT_SCALE;
                s = s * m - NEGV * (1.f - m);
                sS[r * 65 + c] = s;
            }
        }
        __syncthreads();
        // softmax per row (pitch 65 -> conflict-free)
        if (tid < 64) {
            float* row = sS + tid * 65;
            float mx = row[0];
            for (int c = 1; c < 64; c++) mx = fmaxf(mx, row[c]);
            float sum = 0.f;
            for (int c = 0; c < 64; c++) { float e = __expf(row[c] - mx); row[c] = e; sum += e; }
            float inv = __fdividef(1.f, sum);
            for (int c = 0; c < 64; c++) row[c] *= inv;
        }
        __syncthreads();
        // O_h = S @ V_h : thread -> (row r, 8 d-cols)
        {
            int r = tid >> 2, dg = tid & 3;
            int d0 = h * DH + dg * 8;
            float a[8];
            #pragma unroll
            for (int j = 0; j < 8; j++) a[j] = 0.f;
            for (int c = 0; c < 64; c++) {
                float s = sS[r * 65 + c];
                float4 v0 = *reinterpret_cast<const float4*>(Vb + c * HID + d0);
                float4 v1 = *reinterpret_cast<const float4*>(Vb + c * HID + d0 + 4);
                a[0] += s * v0.x; a[1] += s * v0.y; a[2] += s * v0.z; a[3] += s * v0.w;
                a[4] += s * v1.x; a[5] += s * v1.y; a[6] += s * v1.z; a[7] += s * v1.w;
            }
            float4 o0 = { a[0], a[1], a[2], a[3] };
            float4 o1 = { a[4], a[5], a[6], a[7] };
            *reinterpret_cast<float4*>(Ob + r * HID + d0)     = o0;
            *reinterpret_cast<float4*>(Ob + r * HID + d0 + 4) = o1;
        }
    }
}

__global__ void __launch_bounds__(TPB, 1)
drgn_kernel(Params p, float* __restrict__ out_qs, float* __restrict__ out_h3)
{
    extern __shared__ float sm[];
    const int tid = threadIdx.x;
    const int b   = blockIdx.x;

    float* B0  = sm + OFF_B0;
    float* B1  = sm + OFF_B1;
    float* B2  = sm + OFF_B2;
    float* B3  = sm + OFF_B3;
    float* sM  = sm + OFF_M;
    float* scr = sm + OFF_SCR;
    uint32_t scr_u32 = (uint32_t)__cvta_generic_to_shared(scr);

    // load x[b] (64x64) into B1 with pitch 128; mask[b] as float
    const float* xb = p.x + (size_t)b * NANT * INDIM;
    for (int i = tid; i < NANT * INDIM; i += TPB)
        B1[(i >> 6) * HID + (i & 63)] = xb[i];
    const int* mb = p.mask + (size_t)b * NANT * NANT;
    for (int i = tid; i < NANT * NANT; i += TPB)
        sM[i] = (float)mb[i];
    // (ordering handled by the first gemm_pass's internal __syncthreads)

    ull acc[32];

    // encoder: xe = relu(x @ enc_w^T + enc_b) -> B0
    zero_acc(acc); gemm_pass<64>(acc, B1, p.enc_w, scr, scr_u32, tid); epi_relu(acc, B0, p.enc_b, tid);

    // ---- MHA layer 1 ----
    zero_acc(acc); gemm_pass<128>(acc, B0, p.q1_w, scr, scr_u32, tid); epi_relu(acc, B1, p.q1_b, tid);
    zero_acc(acc); gemm_pass<128>(acc, B0, p.k1_w, scr, scr_u32, tid); epi_relu(acc, B2, p.k1_b, tid);
    zero_acc(acc); gemm_pass<128>(acc, B0, p.v1_w, scr, scr_u32, tid); epi_relu(acc, B3, p.v1_b, tid);
    attention(B1, B2, B3, B0, sM, scr, tid);                 // O -> B0
    zero_acc(acc); gemm_pass<128>(acc, B0, p.o1_w, scr, scr_u32, tid); epi_relu(acc, B1, p.o1_b, tid); // h1 -> B1

    // ---- MHA layer 2 ----
    zero_acc(acc); gemm_pass<128>(acc, B1, p.q2_w, scr, scr_u32, tid); epi_relu(acc, B0, p.q2_b, tid);
    zero_acc(acc); gemm_pass<128>(acc, B1, p.k2_w, scr, scr_u32, tid); epi_relu(acc, B2, p.k2_b, tid);
    zero_acc(acc); gemm_pass<128>(acc, B1, p.v2_w, scr, scr_u32, tid); epi_relu(acc, B3, p.v2_b, tid);
    attention(B0, B2, B3, B1, sM, scr, tid);                 // O -> B1
    zero_acc(acc); gemm_pass<128>(acc, B1, p.o2_w, scr, scr_u32, tid); epi_relu(acc, B0, p.o2_b, tid); // h2 -> B0

    // ---- GRU (single accumulator; h2 in B0) ----
    __syncthreads();   // all reads of B1 (o2 input) done before overwrite
    const float* hb = p.hidden + (size_t)b * NANT * HID;
    for (int i = tid; i < NANT * HID; i += TPB) B1[i] = hb[i];

    // r = sigmoid(h2@Wih_r^T + H@Whh_r^T + b) -> B2
    zero_acc(acc);
    gemm_pass<128>(acc, B0, p.w_ih,              scr, scr_u32, tid);
    gemm_pass<128>(acc, B1, p.w_hh,              scr, scr_u32, tid);
    epi_sigmoid(acc, B2, p.b_ih, p.b_hh, tid);
    // z -> B3
    zero_acc(acc);
    gemm_pass<128>(acc, B0, p.w_ih + 128 * 128,  scr, scr_u32, tid);
    gemm_pass<128>(acc, B1, p.w_hh + 128 * 128,  scr, scr_u32, tid);
    epi_sigmoid(acc, B3, p.b_ih + 128, p.b_hh + 128, tid);
    // h_n: B2 <- r * (H@Whh_n^T + b_hh_n)    (in place over r; same-thread)
    zero_acc(acc);
    gemm_pass<128>(acc, B1, p.w_hh + 2 * 128 * 128, scr, scr_u32, tid);
    epi_rhn(acc, B2, p.b_hh + 256, tid);
    // i_n + final: h3 -> B2
    zero_acc(acc);
    gemm_pass<128>(acc, B0, p.w_ih + 2 * 128 * 128, scr, scr_u32, tid);
    epi_gru_final(acc, B1, B2, B3, p.b_ih + 256, tid);
    __syncthreads();

    // ---- outputs: h3 and qs = h3 @ lin_w^T + lin_b ----
    float* ho = out_h3 + (size_t)b * NANT * HID;
    for (int i = tid; i < NANT * HID; i += TPB) ho[i] = B2[i];

    float* qo = out_qs + (size_t)b * NANT * ACTD;
    for (int idx = tid; idx < NANT * ACTD; idx += TPB) {
        int r = idx / ACTD;
        int c = idx - r * ACTD;
        const float* hr = B2 + r * HID;
        const float* wr = p.lin_w + c * HID;
        float s = p.lin_b[c];
        #pragma unroll 4
        for (int k = 0; k < HID; k += 4) {
            float4 hv = *reinterpret_cast<const float4*>(hr + k);
            float4 wv = *reinterpret_cast<const float4*>(wr + k);
            s += hv.x * wv.x + hv.y * wv.y + hv.z * wv.z + hv.w * wv.w;
        }
        qo[idx] = s;
    }
}

extern "C" void kernel_launch(void* const* d_in, const int* in_sizes, int n_in,
                              void* d_out, int out_size)
{
    (void)in_sizes; (void)n_in; (void)out_size;
    Params p;
    p.x      = (const float*)d_in[0];
    p.mask   = (const int*)  d_in[1];
    p.hidden = (const float*)d_in[2];
    p.enc_w  = (const float*)d_in[3];  p.enc_b = (const float*)d_in[4];
    p.q1_w   = (const float*)d_in[5];  p.q1_b  = (const float*)d_in[6];
    p.k1_w   = (const float*)d_in[7];  p.k1_b  = (const float*)d_in[8];
    p.v1_w   = (const float*)d_in[9];  p.v1_b  = (const float*)d_in[10];
    p.o1_w   = (const float*)d_in[11]; p.o1_b  = (const float*)d_in[12];
    p.q2_w   = (const float*)d_in[13]; p.q2_b  = (const float*)d_in[14];
    p.k2_w   = (const float*)d_in[15]; p.k2_b  = (const float*)d_in[16];
    p.v2_w   = (const float*)d_in[17]; p.v2_b  = (const float*)d_in[18];
    p.o2_w   = (const float*)d_in[19]; p.o2_b  = (const float*)d_in[20];
    p.w_ih   = (const float*)d_in[21]; p.w_hh  = (const float*)d_in[22];
    p.b_ih   = (const float*)d_in[23]; p.b_hh  = (const float*)d_in[24];
    p.lin_w  = (const float*)d_in[25]; p.lin_b = (const float*)d_in[26];

    float* out_qs = (float*)d_out;                                  // [4096,64,20]
    float* out_h3 = (float*)d_out + (size_t)BS * NANT * ACTD;       // [4096,64,128]

    cudaFuncSetAttribute(drgn_kernel,
                         cudaFuncAttributeMaxDynamicSharedMemorySize, SMEM_BYTES);
    drgn_kernel<<<BS, TPB, SMEM_BYTES>>>(p, out_qs, out_h3);
}